// round 8
// baseline (speedup 1.0000x reference)
#include <cuda_runtime.h>
#include <cuda_bf16.h>
#include <math.h>

// Problem constants
#define NN      50000      // nodes
#define EE      800000     // edges (before self loops)
#define ET      850000     // edges + self loops
#define FIN     64
#define HH      128
#define GG      512
#define NEG     0.2f

#define NB_SCAN 196        // ceil(NN/256)

// ---------------- scratch (device globals; referenced by symbol only) ---------
__device__ __align__(256) float g_xl[NN * HH];
__device__ __align__(256) float g_xr[NN * HH];
__device__ __align__(256) float g_h1[NN * HH];
__device__ int   g_counts[NN];
__device__ int   g_off[NN + 1];
__device__ int   g_cursor[NN];
__device__ int   g_srclist[ET];
__device__ int   g_blockTot[256];
__device__ int   g_blockOff[256];
__device__ float g_sums[GG];
__device__ float g_cnt[GG];

// ---------------- init ----------------
__global__ void init_kernel() {
    int i = blockIdx.x * blockDim.x + threadIdx.x;
    if (i < NN) g_counts[i] = 0;
    if (i < GG) { g_sums[i] = 0.f; g_cnt[i] = 0.f; }
}

// ---------------- CSR build ----------------
// NOTE: edge_index/batch are int32 on this pipeline (JAX x64 disabled downcasts
// jnp.int64 -> int32). Reading them as int64 produced garbage indices whose
// atomics trapped with error 717 (rounds 4-7).
__global__ void count_kernel(const int* __restrict__ ei) {
    int i = blockIdx.x * blockDim.x + threadIdx.x;
    if (i >= ET) return;
    int d = (i < EE) ? ei[EE + i] : (i - EE);
    atomicAdd(&g_counts[d], 1);
}

__global__ void scan_block_tot() {
    __shared__ int sm[256];
    int i = blockIdx.x * 256 + threadIdx.x;
    int v = (i < NN) ? g_counts[i] : 0;
    sm[threadIdx.x] = v;
    __syncthreads();
    for (int st = 128; st > 0; st >>= 1) {
        if (threadIdx.x < st) sm[threadIdx.x] += sm[threadIdx.x + st];
        __syncthreads();
    }
    if (threadIdx.x == 0) g_blockTot[blockIdx.x] = sm[0];
}

__global__ void scan_block_off() {
    __shared__ int sm[256];
    int t = threadIdx.x;
    int v = (t < NB_SCAN) ? g_blockTot[t] : 0;
    sm[t] = v;
    __syncthreads();
    for (int st = 1; st < 256; st <<= 1) {
        int a = (t >= st) ? sm[t - st] : 0;
        __syncthreads();
        sm[t] += a;
        __syncthreads();
    }
    if (t < NB_SCAN) g_blockOff[t] = sm[t] - v;   // exclusive
}

__global__ void scan_write_off() {
    __shared__ int sm[256];
    int t = threadIdx.x;
    int i = blockIdx.x * 256 + t;
    int v = (i < NN) ? g_counts[i] : 0;
    sm[t] = v;
    __syncthreads();
    for (int st = 1; st < 256; st <<= 1) {
        int a = (t >= st) ? sm[t - st] : 0;
        __syncthreads();
        sm[t] += a;
        __syncthreads();
    }
    if (i < NN) {
        int ex = g_blockOff[blockIdx.x] + sm[t] - v;
        g_off[i] = ex;
        g_cursor[i] = ex;
    }
    if (i == 0) g_off[NN] = ET;
}

__global__ void fill_kernel(const int* __restrict__ ei) {
    int i = blockIdx.x * blockDim.x + threadIdx.x;
    if (i >= ET) return;
    int s, d;
    if (i < EE) { s = ei[i]; d = ei[EE + i]; }
    else        { s = d = i - EE; }
    int pos = atomicAdd(&g_cursor[d], 1);
    g_srclist[pos] = s;
}

// ---------------- SGEMM pair: {g_xl,g_xr}[nrows,128] = X @ W{l,r} + b{l,r} ----
// blockIdx.y selects (W, bias, output global). X_FROM_H1: read g_h1 (layer 2)
// instead of the harness input pointer. block tile 64x128, thread tile 4x8.
template<int K, bool X_FROM_H1>
__global__ __launch_bounds__(256) void gemm_pair_kernel(
    const float* __restrict__ Xin,
    const float* __restrict__ Wl, const float* __restrict__ bl,
    const float* __restrict__ Wr, const float* __restrict__ br,
    int nrows)
{
    __shared__ float4 Ws4[64 * 32];   // W tile [64][128] as float4 (32KB)
    __shared__ float  Xs[64 * 64];    // X tile [row][k] (16KB)

    const float* X    = X_FROM_H1 ? g_h1 : Xin;
    const float* W    = blockIdx.y ? Wr : Wl;
    const float* bias = blockIdx.y ? br : bl;
    float*       Y    = blockIdx.y ? g_xr : g_xl;

    const int tid = threadIdx.x;
    const int tx = tid & 15;          // col group (8 cols each)
    const int ty = tid >> 4;          // row group (4 rows each)
    const int row0 = blockIdx.x * 64;

    float acc[4][8];
    #pragma unroll
    for (int i = 0; i < 4; i++)
        #pragma unroll
        for (int j = 0; j < 8; j++) acc[i][j] = 0.f;

    for (int kt = 0; kt < K; kt += 64) {
        #pragma unroll
        for (int t = 0; t < 8; t++) {
            int li = tid + t * 256;              // = k*32 + c4
            int k = li >> 5, c4 = li & 31;
            Ws4[li] = ((const float4*)(W + (size_t)(kt + k) * 128))[c4];
        }
        #pragma unroll
        for (int t = 0; t < 16; t++) {
            int li = tid + t * 256;
            int r = li >> 6, k = li & 63;
            int row = row0 + r;
            float v = (row < nrows) ? X[(size_t)row * K + kt + k] : 0.f;
            Xs[r * 64 + k] = v;
        }
        __syncthreads();

        #pragma unroll 8
        for (int k = 0; k < 64; k++) {
            float xv[4];
            #pragma unroll
            for (int i = 0; i < 4; i++) xv[i] = Xs[(ty * 4 + i) * 64 + k];
            float4 w0 = Ws4[k * 32 + tx * 2];
            float4 w1 = Ws4[k * 32 + tx * 2 + 1];
            #pragma unroll
            for (int i = 0; i < 4; i++) {
                acc[i][0] = fmaf(xv[i], w0.x, acc[i][0]);
                acc[i][1] = fmaf(xv[i], w0.y, acc[i][1]);
                acc[i][2] = fmaf(xv[i], w0.z, acc[i][2]);
                acc[i][3] = fmaf(xv[i], w0.w, acc[i][3]);
                acc[i][4] = fmaf(xv[i], w1.x, acc[i][4]);
                acc[i][5] = fmaf(xv[i], w1.y, acc[i][5]);
                acc[i][6] = fmaf(xv[i], w1.z, acc[i][6]);
                acc[i][7] = fmaf(xv[i], w1.w, acc[i][7]);
            }
        }
        __syncthreads();
    }

    float4 b0 = ((const float4*)bias)[tx * 2];
    float4 b1 = ((const float4*)bias)[tx * 2 + 1];
    #pragma unroll
    for (int i = 0; i < 4; i++) {
        int row = row0 + ty * 4 + i;
        if (row < nrows) {
            float4 o0 = make_float4(acc[i][0] + b0.x, acc[i][1] + b0.y,
                                    acc[i][2] + b0.z, acc[i][3] + b0.w);
            float4 o1 = make_float4(acc[i][4] + b1.x, acc[i][5] + b1.y,
                                    acc[i][6] + b1.z, acc[i][7] + b1.w);
            float4* yp = (float4*)(Y + (size_t)row * 128);
            yp[tx * 2]     = o0;
            yp[tx * 2 + 1] = o1;
        }
    }
}

// ---------------- GATv2 edge phase: one warp per destination node ----------------
// reads g_xl/g_xr by symbol; online softmax over CSR bucket, weighted sum of
// xl[src], +bias, ReLU. FUSE_POOL: dot with Wlin and accumulate per-graph
// mean-pool numerator/denominator instead of writing the node vector to g_h1.
template<bool FUSE_POOL>
__global__ __launch_bounds__(256) void attn_kernel(
    const float* __restrict__ att, const float* __restrict__ bias,
    const float* __restrict__ Wlin,          // used when FUSE_POOL
    const int* __restrict__ batch)           // used when FUSE_POOL
{
    if (!FUSE_POOL) { (void)Wlin; (void)batch; }

    int w = (blockIdx.x * blockDim.x + threadIdx.x) >> 5;
    int lane = threadIdx.x & 31;
    if (w >= NN) return;

    const float4 xr4  = *(const float4*)(g_xr + (size_t)w * 128 + lane * 4);
    const float4 att4 = *(const float4*)(att + lane * 4);
    int o0 = g_off[w], o1 = g_off[w + 1];

    float m = -3.0e38f, den = 0.f;
    float4 acc = make_float4(0.f, 0.f, 0.f, 0.f);

    // every node has a self loop -> o1 > o0 always
    int src = g_srclist[o0];
    float4 v = *(const float4*)(g_xl + (size_t)src * 128 + lane * 4);

    for (int s = o0; s < o1; s++) {
        float4 vc = v;
        if (s + 1 < o1) {
            int sn = g_srclist[s + 1];
            v = *(const float4*)(g_xl + (size_t)sn * 128 + lane * 4);  // prefetch
        }
        float ex = vc.x + xr4.x, ey = vc.y + xr4.y;
        float ez = vc.z + xr4.z, ew = vc.w + xr4.w;
        ex = (ex > 0.f) ? ex : ex * NEG;
        ey = (ey > 0.f) ? ey : ey * NEG;
        ez = (ez > 0.f) ? ez : ez * NEG;
        ew = (ew > 0.f) ? ew : ew * NEG;
        float pd = fmaf(ex, att4.x, fmaf(ey, att4.y, fmaf(ez, att4.z, ew * att4.w)));
        #pragma unroll
        for (int o = 16; o > 0; o >>= 1)
            pd += __shfl_xor_sync(0xffffffffu, pd, o);

        float nm = fmaxf(m, pd);
        float sc = __expf(m - nm);
        float p  = __expf(pd - nm);
        den = den * sc + p;
        acc.x = fmaf(p, vc.x, acc.x * sc);
        acc.y = fmaf(p, vc.y, acc.y * sc);
        acc.z = fmaf(p, vc.z, acc.z * sc);
        acc.w = fmaf(p, vc.w, acc.w * sc);
        m = nm;
    }

    float inv = 1.f / den;
    float4 b4 = *(const float4*)(bias + lane * 4);
    float4 o4;
    o4.x = fmaxf(fmaf(acc.x, inv, b4.x), 0.f);
    o4.y = fmaxf(fmaf(acc.y, inv, b4.y), 0.f);
    o4.z = fmaxf(fmaf(acc.z, inv, b4.z), 0.f);
    o4.w = fmaxf(fmaf(acc.w, inv, b4.w), 0.f);

    if (!FUSE_POOL) {
        *(float4*)(g_h1 + (size_t)w * 128 + lane * 4) = o4;
    } else {
        float4 wv = *(const float4*)(Wlin + lane * 4);
        float pd = fmaf(o4.x, wv.x, fmaf(o4.y, wv.y, fmaf(o4.z, wv.z, o4.w * wv.w)));
        #pragma unroll
        for (int o = 16; o > 0; o >>= 1)
            pd += __shfl_xor_sync(0xffffffffu, pd, o);
        if (lane == 0) {
            int g = batch[w];
            atomicAdd(&g_sums[g], pd);
            atomicAdd(&g_cnt[g], 1.f);
        }
    }
}

__global__ void final_kernel(const float* __restrict__ blin, float* __restrict__ out) {
    int g = blockIdx.x * blockDim.x + threadIdx.x;
    if (g < GG) out[g] = g_sums[g] / fmaxf(g_cnt[g], 1.f) + blin[0];
}

// ---------------- launch ----------------
extern "C" void kernel_launch(void* const* d_in, const int* in_sizes, int n_in,
                              void* d_out, int out_size) {
    const float* x     = (const float*)d_in[0];
    const int*   ei    = (const int*)d_in[1];     // int32 (JAX x64 disabled)
    const int*   batch = (const int*)d_in[3];     // int32
    const float* Wl1 = (const float*)d_in[4],  *bl1 = (const float*)d_in[5];
    const float* Wr1 = (const float*)d_in[6],  *br1 = (const float*)d_in[7];
    const float* att1= (const float*)d_in[8],  *b1  = (const float*)d_in[9];
    const float* Wl2 = (const float*)d_in[10], *bl2 = (const float*)d_in[11];
    const float* Wr2 = (const float*)d_in[12], *br2 = (const float*)d_in[13];
    const float* att2= (const float*)d_in[14], *b2  = (const float*)d_in[15];
    const float* Wlin= (const float*)d_in[16], *blin= (const float*)d_in[17];
    float* out = (float*)d_out;

    const int edgeBlocks = (ET + 255) / 256;
    const int warpBlocks = (NN * 32 + 255) / 256;   // one warp per node
    dim3 gemmGrid((NN + 63) / 64, 2);

    // CSR build (recomputed every call: deterministic work, no caching)
    init_kernel<<<(NN + 255) / 256, 256>>>();
    count_kernel<<<edgeBlocks, 256>>>(ei);
    scan_block_tot<<<NB_SCAN, 256>>>();
    scan_block_off<<<1, 256>>>();
    scan_write_off<<<NB_SCAN, 256>>>();
    fill_kernel<<<edgeBlocks, 256>>>(ei);

    // layer 1: xl/xr <- x @ W{l,r}1 + b ; h1 <- attention
    gemm_pair_kernel<FIN, false><<<gemmGrid, 256>>>(x, Wl1, bl1, Wr1, br1, NN);
    attn_kernel<false><<<warpBlocks, 256>>>(att1, b1, nullptr, nullptr);

    // layer 2: xl/xr <- h1 @ W{l,r}2 + b ; attention fused with pool+head
    gemm_pair_kernel<HH, true><<<gemmGrid, 256>>>(nullptr, Wl2, bl2, Wr2, br2, NN);
    attn_kernel<true><<<warpBlocks, 256>>>(att2, b2, Wlin, batch);

    // head bias + mean division
    final_kernel<<<2, 256>>>(blin, out);
}

// round 9
// speedup vs baseline: 1.2278x; 1.2278x over previous
#include <cuda_runtime.h>
#include <cuda_bf16.h>
#include <math.h>

// Problem constants
#define NN      50000      // nodes
#define EE      800000     // edges (before self loops)
#define ET      850000     // edges + self loops
#define FIN     64
#define HH      128
#define GG      512
#define NEG     0.2f

#define NB_SCAN 196        // ceil(NN/256)

// ---------------- scratch (device globals; referenced by symbol only) ---------
__device__ __align__(256) float g_xl[NN * HH];
__device__ __align__(256) float g_xr[NN * HH];
__device__ __align__(256) float g_h1[NN * HH];
__device__ int   g_counts[NN];
__device__ int   g_off[NN + 1];
__device__ int   g_cursor[NN];
__device__ int   g_srclist[ET];
__device__ int   g_blockTot[256];
__device__ int   g_blockOff[256];
__device__ float g_sums[GG];
__device__ float g_cnt[GG];

// ---------------- init ----------------
__global__ void init_kernel() {
    int i = blockIdx.x * blockDim.x + threadIdx.x;
    if (i < NN) g_counts[i] = 0;
    if (i < GG) { g_sums[i] = 0.f; g_cnt[i] = 0.f; }
}

// ---------------- CSR build (edge_index/batch are int32) ----------------
__global__ void count_kernel(const int* __restrict__ ei) {
    int i = blockIdx.x * blockDim.x + threadIdx.x;
    if (i >= ET) return;
    int d = (i < EE) ? ei[EE + i] : (i - EE);
    atomicAdd(&g_counts[d], 1);
}

__global__ void scan_block_tot() {
    __shared__ int sm[256];
    int i = blockIdx.x * 256 + threadIdx.x;
    int v = (i < NN) ? g_counts[i] : 0;
    sm[threadIdx.x] = v;
    __syncthreads();
    for (int st = 128; st > 0; st >>= 1) {
        if (threadIdx.x < st) sm[threadIdx.x] += sm[threadIdx.x + st];
        __syncthreads();
    }
    if (threadIdx.x == 0) g_blockTot[blockIdx.x] = sm[0];
}

__global__ void scan_block_off() {
    __shared__ int sm[256];
    int t = threadIdx.x;
    int v = (t < NB_SCAN) ? g_blockTot[t] : 0;
    sm[t] = v;
    __syncthreads();
    for (int st = 1; st < 256; st <<= 1) {
        int a = (t >= st) ? sm[t - st] : 0;
        __syncthreads();
        sm[t] += a;
        __syncthreads();
    }
    if (t < NB_SCAN) g_blockOff[t] = sm[t] - v;   // exclusive
}

__global__ void scan_write_off() {
    __shared__ int sm[256];
    int t = threadIdx.x;
    int i = blockIdx.x * 256 + t;
    int v = (i < NN) ? g_counts[i] : 0;
    sm[t] = v;
    __syncthreads();
    for (int st = 1; st < 256; st <<= 1) {
        int a = (t >= st) ? sm[t - st] : 0;
        __syncthreads();
        sm[t] += a;
        __syncthreads();
    }
    if (i < NN) {
        int ex = g_blockOff[blockIdx.x] + sm[t] - v;
        g_off[i] = ex;
        g_cursor[i] = ex;
    }
    if (i == 0) g_off[NN] = ET;
}

__global__ void fill_kernel(const int* __restrict__ ei) {
    int i = blockIdx.x * blockDim.x + threadIdx.x;
    if (i >= ET) return;
    int s, d;
    if (i < EE) { s = ei[i]; d = ei[EE + i]; }
    else        { s = d = i - EE; }
    int pos = atomicAdd(&g_cursor[d], 1);
    g_srclist[pos] = s;
}

// ---------------- SGEMM pair: {g_xl,g_xr}[nrows,128] = X @ W{l,r} + b{l,r} ----
// 128x128 block tile, 8x8 thread tile (split 2x2 of 4x4 for conflict-free LDS),
// BK=32. blockIdx.y selects (W, bias, output). X_FROM_H1: layer-2 reads g_h1.
template<int K, bool X_FROM_H1>
__global__ __launch_bounds__(256) void gemm_pair_kernel(
    const float* __restrict__ Xin,
    const float* __restrict__ Wl, const float* __restrict__ bl,
    const float* __restrict__ Wr, const float* __restrict__ br,
    int nrows)
{
    __shared__ float Xs[32][128];   // [k][row]  (transposed stage) 16KB
    __shared__ float Ws[32][128];   // [k][col]                      16KB

    const float* X    = X_FROM_H1 ? g_h1 : Xin;
    const float* W    = blockIdx.y ? Wr : Wl;
    const float* bias = blockIdx.y ? br : bl;
    float*       Y    = blockIdx.y ? g_xr : g_xl;

    const int tid = threadIdx.x;
    const int tx = tid & 15;          // col group
    const int ty = tid >> 4;          // row group
    const int row0 = blockIdx.x * 128;

    float acc[8][8];
    #pragma unroll
    for (int i = 0; i < 8; i++)
        #pragma unroll
        for (int j = 0; j < 8; j++) acc[i][j] = 0.f;

    for (int kt = 0; kt < K; kt += 32) {
        // X tile: 128 rows x 32 k -> transposed into Xs[k][row].
        // 1024 float4 loads; each thread does 4 (li = tid + p*256).
        #pragma unroll
        for (int p = 0; p < 4; p++) {
            int li = tid + p * 256;
            int r  = li >> 3;          // 0..127
            int c4 = li & 7;           // float4 index within 32 k
            int row = row0 + r;
            float4 v = make_float4(0.f, 0.f, 0.f, 0.f);
            if (row < nrows)
                v = *(const float4*)(X + (size_t)row * K + kt + c4 * 4);
            int kk = c4 * 4;
            Xs[kk + 0][r] = v.x;
            Xs[kk + 1][r] = v.y;
            Xs[kk + 2][r] = v.z;
            Xs[kk + 3][r] = v.w;
        }
        // W tile: rows kt..kt+31 of W[K][128], direct float4 copy.
        #pragma unroll
        for (int p = 0; p < 4; p++) {
            int li = tid + p * 256;
            int k  = li >> 5;          // 0..31
            int c4 = li & 31;          // float4 col index
            *(float4*)&Ws[k][c4 * 4] =
                *(const float4*)(W + (size_t)(kt + k) * 128 + c4 * 4);
        }
        __syncthreads();

        #pragma unroll
        for (int k = 0; k < 32; k++) {
            float4 x0 = *(float4*)&Xs[k][ty * 4];
            float4 x1 = *(float4*)&Xs[k][64 + ty * 4];
            float4 w0 = *(float4*)&Ws[k][tx * 4];
            float4 w1 = *(float4*)&Ws[k][64 + tx * 4];
            float xv[8] = {x0.x, x0.y, x0.z, x0.w, x1.x, x1.y, x1.z, x1.w};
            float wv[8] = {w0.x, w0.y, w0.z, w0.w, w1.x, w1.y, w1.z, w1.w};
            #pragma unroll
            for (int i = 0; i < 8; i++)
                #pragma unroll
                for (int j = 0; j < 8; j++)
                    acc[i][j] = fmaf(xv[i], wv[j], acc[i][j]);
        }
        __syncthreads();
    }

    float4 bias4[2];
    bias4[0] = *(const float4*)(bias + tx * 4);
    bias4[1] = *(const float4*)(bias + 64 + tx * 4);

    #pragma unroll
    for (int a = 0; a < 2; a++) {
        #pragma unroll
        for (int i = 0; i < 4; i++) {
            int row = row0 + a * 64 + ty * 4 + i;
            if (row >= nrows) continue;
            #pragma unroll
            for (int b = 0; b < 2; b++) {
                float4 o;
                o.x = acc[a * 4 + i][b * 4 + 0] + bias4[b].x;
                o.y = acc[a * 4 + i][b * 4 + 1] + bias4[b].y;
                o.z = acc[a * 4 + i][b * 4 + 2] + bias4[b].z;
                o.w = acc[a * 4 + i][b * 4 + 3] + bias4[b].w;
                *(float4*)(Y + (size_t)row * 128 + b * 64 + tx * 4) = o;
            }
        }
    }
}

// ---------------- GATv2 edge phase: one warp per destination node ----------------
// reads g_xl/g_xr by symbol; online softmax over CSR bucket, weighted sum of
// xl[src], +bias, ReLU. FUSE_POOL: dot with Wlin and accumulate per-graph
// mean-pool numerator/denominator instead of writing the node vector to g_h1.
template<bool FUSE_POOL>
__global__ __launch_bounds__(256) void attn_kernel(
    const float* __restrict__ att, const float* __restrict__ bias,
    const float* __restrict__ Wlin,          // used when FUSE_POOL
    const int* __restrict__ batch)           // used when FUSE_POOL
{
    if (!FUSE_POOL) { (void)Wlin; (void)batch; }

    int w = (blockIdx.x * blockDim.x + threadIdx.x) >> 5;
    int lane = threadIdx.x & 31;
    if (w >= NN) return;

    const float4 xr4  = *(const float4*)(g_xr + (size_t)w * 128 + lane * 4);
    const float4 att4 = *(const float4*)(att + lane * 4);
    int o0 = g_off[w], o1 = g_off[w + 1];

    float m = -3.0e38f, den = 0.f;
    float4 acc = make_float4(0.f, 0.f, 0.f, 0.f);

    // every node has a self loop -> o1 > o0 always
    int src = g_srclist[o0];
    float4 v = *(const float4*)(g_xl + (size_t)src * 128 + lane * 4);

    for (int s = o0; s < o1; s++) {
        float4 vc = v;
        if (s + 1 < o1) {
            int sn = g_srclist[s + 1];
            v = *(const float4*)(g_xl + (size_t)sn * 128 + lane * 4);  // prefetch
        }
        float ex = vc.x + xr4.x, ey = vc.y + xr4.y;
        float ez = vc.z + xr4.z, ew = vc.w + xr4.w;
        ex = (ex > 0.f) ? ex : ex * NEG;
        ey = (ey > 0.f) ? ey : ey * NEG;
        ez = (ez > 0.f) ? ez : ez * NEG;
        ew = (ew > 0.f) ? ew : ew * NEG;
        float pd = fmaf(ex, att4.x, fmaf(ey, att4.y, fmaf(ez, att4.z, ew * att4.w)));
        #pragma unroll
        for (int o = 16; o > 0; o >>= 1)
            pd += __shfl_xor_sync(0xffffffffu, pd, o);

        float nm = fmaxf(m, pd);
        float sc = __expf(m - nm);
        float p  = __expf(pd - nm);
        den = den * sc + p;
        acc.x = fmaf(p, vc.x, acc.x * sc);
        acc.y = fmaf(p, vc.y, acc.y * sc);
        acc.z = fmaf(p, vc.z, acc.z * sc);
        acc.w = fmaf(p, vc.w, acc.w * sc);
        m = nm;
    }

    float inv = 1.f / den;
    float4 b4 = *(const float4*)(bias + lane * 4);
    float4 o4;
    o4.x = fmaxf(fmaf(acc.x, inv, b4.x), 0.f);
    o4.y = fmaxf(fmaf(acc.y, inv, b4.y), 0.f);
    o4.z = fmaxf(fmaf(acc.z, inv, b4.z), 0.f);
    o4.w = fmaxf(fmaf(acc.w, inv, b4.w), 0.f);

    if (!FUSE_POOL) {
        *(float4*)(g_h1 + (size_t)w * 128 + lane * 4) = o4;
    } else {
        float4 wv = *(const float4*)(Wlin + lane * 4);
        float pd = fmaf(o4.x, wv.x, fmaf(o4.y, wv.y, fmaf(o4.z, wv.z, o4.w * wv.w)));
        #pragma unroll
        for (int o = 16; o > 0; o >>= 1)
            pd += __shfl_xor_sync(0xffffffffu, pd, o);
        if (lane == 0) {
            int g = batch[w];
            atomicAdd(&g_sums[g], pd);
            atomicAdd(&g_cnt[g], 1.f);
        }
    }
}

__global__ void final_kernel(const float* __restrict__ blin, float* __restrict__ out) {
    int g = blockIdx.x * blockDim.x + threadIdx.x;
    if (g < GG) out[g] = g_sums[g] / fmaxf(g_cnt[g], 1.f) + blin[0];
}

// ---------------- launch ----------------
extern "C" void kernel_launch(void* const* d_in, const int* in_sizes, int n_in,
                              void* d_out, int out_size) {
    const float* x     = (const float*)d_in[0];
    const int*   ei    = (const int*)d_in[1];     // int32 (JAX x64 disabled)
    const int*   batch = (const int*)d_in[3];     // int32
    const float* Wl1 = (const float*)d_in[4],  *bl1 = (const float*)d_in[5];
    const float* Wr1 = (const float*)d_in[6],  *br1 = (const float*)d_in[7];
    const float* att1= (const float*)d_in[8],  *b1  = (const float*)d_in[9];
    const float* Wl2 = (const float*)d_in[10], *bl2 = (const float*)d_in[11];
    const float* Wr2 = (const float*)d_in[12], *br2 = (const float*)d_in[13];
    const float* att2= (const float*)d_in[14], *b2  = (const float*)d_in[15];
    const float* Wlin= (const float*)d_in[16], *blin= (const float*)d_in[17];
    float* out = (float*)d_out;

    const int edgeBlocks = (ET + 255) / 256;
    const int warpBlocks = (NN * 32 + 255) / 256;   // one warp per node
    dim3 gemmGrid((NN + 127) / 128, 2);

    // CSR build (recomputed every call: deterministic work, no caching)
    init_kernel<<<(NN + 255) / 256, 256>>>();
    count_kernel<<<edgeBlocks, 256>>>(ei);
    scan_block_tot<<<NB_SCAN, 256>>>();
    scan_block_off<<<1, 256>>>();
    scan_write_off<<<NB_SCAN, 256>>>();
    fill_kernel<<<edgeBlocks, 256>>>(ei);

    // layer 1: xl/xr <- x @ W{l,r}1 + b ; h1 <- attention
    gemm_pair_kernel<FIN, false><<<gemmGrid, 256>>>(x, Wl1, bl1, Wr1, br1, NN);
    attn_kernel<false><<<warpBlocks, 256>>>(att1, b1, nullptr, nullptr);

    // layer 2: xl/xr <- h1 @ W{l,r}2 + b ; attention fused with pool+head
    gemm_pair_kernel<HH, true><<<gemmGrid, 256>>>(nullptr, Wl2, bl2, Wr2, br2, NN);
    attn_kernel<true><<<warpBlocks, 256>>>(att2, b2, Wlin, batch);

    // head bias + mean division
    final_kernel<<<2, 256>>>(blin, out);
}